// round 1
// baseline (speedup 1.0000x reference)
#include <cuda_runtime.h>

#define B_ 4
#define L_ 1024
#define H_ 8
#define E_ 64
#define PLANE (1024*1024)

// 128 MB scratch each (zero-initialized .bss; never-written regions stay 0 deterministically)
__device__ float g_buf1[(size_t)B_*H_*L_*L_];
__device__ float g_buf2[(size_t)B_*H_*L_*L_];

// ---------------------------------------------------------------------------
// Pass A: S1[b,h,l,s] = (Q.K^T)*scale, causal zeroed. Writes ALL tiles (zeros
// in masked region) so conv halos downstream read clean zeros.
// grid (16,16,32), block (16,16). 64x64 tile, 4x4 per thread.
// ---------------------------------------------------------------------------
__global__ void qk_kernel(const float* __restrict__ q, const float* __restrict__ k)
{
    const int bh = blockIdx.z;
    const int b  = bh >> 3, h = bh & 7;
    const int l0 = blockIdx.y << 6, s0 = blockIdx.x << 6;
    const int tx = threadIdx.x, ty = threadIdx.y;
    const int tid = ty * 16 + tx;
    float* outp = g_buf1 + (size_t)bh * PLANE;

    if (s0 > l0 + 63) {                 // fully masked tile -> zeros only
        const float4 z = make_float4(0.f, 0.f, 0.f, 0.f);
        #pragma unroll
        for (int i = 0; i < 4; i++) {
            int row = (tid >> 4) + (i << 4);
            int c   = (tid & 15) << 2;
            *(float4*)&outp[(size_t)(l0 + row) * 1024 + s0 + c] = z;
        }
        return;
    }

    __shared__ float Qs[64][65];
    __shared__ float Ks[64][65];
    const float* qb = q + (size_t)b * L_ * (H_ * E_) + h * E_;
    const float* kb = k + (size_t)b * L_ * (H_ * E_) + h * E_;

    #pragma unroll
    for (int i = 0; i < 4; i++) {
        int row = (tid >> 4) + (i << 4);
        int c   = (tid & 15) << 2;
        float4 qv = *(const float4*)&qb[(size_t)(l0 + row) * 512 + c];
        Qs[row][c] = qv.x; Qs[row][c+1] = qv.y; Qs[row][c+2] = qv.z; Qs[row][c+3] = qv.w;
        float4 kv = *(const float4*)&kb[(size_t)(s0 + row) * 512 + c];
        Ks[row][c] = kv.x; Ks[row][c+1] = kv.y; Ks[row][c+2] = kv.z; Ks[row][c+3] = kv.w;
    }
    __syncthreads();

    float acc[4][4];
    #pragma unroll
    for (int i = 0; i < 4; i++)
        #pragma unroll
        for (int j = 0; j < 4; j++) acc[i][j] = 0.f;

    #pragma unroll
    for (int e = 0; e < 64; e++) {
        float qv[4], kv[4];
        #pragma unroll
        for (int i = 0; i < 4; i++) qv[i] = Qs[ty * 4 + i][e];
        #pragma unroll
        for (int j = 0; j < 4; j++) kv[j] = Ks[tx * 4 + j][e];
        #pragma unroll
        for (int i = 0; i < 4; i++)
            #pragma unroll
            for (int j = 0; j < 4; j++) acc[i][j] += qv[i] * kv[j];
    }

    const float scale = 0.125f;  // 1/sqrt(64)
    #pragma unroll
    for (int i = 0; i < 4; i++) {
        int l = l0 + ty * 4 + i;
        int sb = s0 + tx * 4;
        float4 r;
        r.x = (sb + 0 <= l) ? acc[i][0] * scale : 0.f;
        r.y = (sb + 1 <= l) ? acc[i][1] * scale : 0.f;
        r.z = (sb + 2 <= l) ? acc[i][2] * scale : 0.f;
        r.w = (sb + 3 <= l) ? acc[i][3] * scale : 0.f;
        *(float4*)&outp[(size_t)l * 1024 + sb] = r;
    }
}

// ---------------------------------------------------------------------------
// Pass B: S2[b,g,l,s] = sum_h wpsm[g,h] * conv3x3(S1[b,h])[l,s]
// conv: out[l,s] = sum_{i,j} k[i,j] * S1[l-2+i, s-1+j]
// grid (32,32,4) [s-tile, l-tile, b], early-exit above diagonal. block 256.
// ---------------------------------------------------------------------------
__global__ void convmix_kernel(const float* __restrict__ mta_k, const float* __restrict__ wpsm)
{
    if (blockIdx.x > blockIdx.y) return;
    const int st = blockIdx.x << 5, lt = blockIdx.y << 5, b = blockIdx.z;
    const int tid = threadIdx.x;

    __shared__ float sm[8][34][35];
    __shared__ float kk[8][9];
    __shared__ float wm[64];
    if (tid < 72) kk[tid / 9][tid % 9] = mta_k[tid];
    if (tid < 64) wm[tid] = wpsm[tid];

    const float* inb = g_buf1 + (size_t)b * 8 * PLANE;
    for (int idx = tid; idx < 8 * 34 * 34; idx += 256) {
        int h = idx / (34 * 34);
        int r = (idx / 34) % 34;
        int c = idx % 34;
        int gl = lt - 2 + r, gs = st - 1 + c;
        float v = 0.f;
        if (gl >= 0 && gs >= 0 && gs < 1024)
            v = inb[(size_t)h * PLANE + (size_t)gl * 1024 + gs];
        sm[h][r][c] = v;
    }
    __syncthreads();

    float* outb = g_buf2 + (size_t)b * 8 * PLANE;
    for (int p = tid; p < 1024; p += 256) {
        int li = p >> 5, si = p & 31;
        float c[8];
        #pragma unroll
        for (int h = 0; h < 8; h++) {
            float a = 0.f;
            #pragma unroll
            for (int i = 0; i < 3; i++)
                #pragma unroll
                for (int j = 0; j < 3; j++)
                    a += kk[h][i * 3 + j] * sm[h][li + i][si + j];
            c[h] = a;
        }
        size_t off = (size_t)(lt + li) * 1024 + (st + si);
        #pragma unroll
        for (int g = 0; g < 8; g++) {
            float a = 0.f;
            #pragma unroll
            for (int h = 0; h < 8; h++) a += wm[g * 8 + h] * c[h];
            outb[(size_t)g * PLANE + off] = a;
        }
    }
}

// ---------------------------------------------------------------------------
// Pass C: row softmax over s in [0, l]. Reads buf2, writes buf1 (only s<=l;
// s>l keeps Pass-A zeros that Pass-D's conv halo needs).
// grid 32768 (= b*8*1024 rows), block 128.
// ---------------------------------------------------------------------------
__global__ void softmax_kernel()
{
    const int row = blockIdx.x;
    const int l = row & 1023;
    const int n = l + 1;
    const float* rp = g_buf2 + (size_t)row * 1024;
    float* op = g_buf1 + (size_t)row * 1024;
    const int tid = threadIdx.x;
    const int wid = tid >> 5, lane = tid & 31;

    float v[8];
    float mx = -1e30f;
    #pragma unroll
    for (int i = 0; i < 8; i++) {
        int s = tid + (i << 7);
        v[i] = (s < n) ? rp[s] : -1e30f;
        mx = fmaxf(mx, v[i]);
    }
    #pragma unroll
    for (int o = 16; o; o >>= 1) mx = fmaxf(mx, __shfl_xor_sync(0xffffffffu, mx, o));

    __shared__ float smax[4];
    __shared__ float ssum[4];
    if (lane == 0) smax[wid] = mx;
    __syncthreads();
    if (wid == 0) {
        float m = (lane < 4) ? smax[lane] : -1e30f;
        #pragma unroll
        for (int o = 2; o; o >>= 1) m = fmaxf(m, __shfl_xor_sync(0xffffffffu, m, o));
        if (lane == 0) smax[0] = m;
    }
    __syncthreads();
    mx = smax[0];

    float sum = 0.f;
    #pragma unroll
    for (int i = 0; i < 8; i++) {
        int s = tid + (i << 7);
        if (s < n) { v[i] = __expf(v[i] - mx); sum += v[i]; }
    }
    #pragma unroll
    for (int o = 16; o; o >>= 1) sum += __shfl_xor_sync(0xffffffffu, sum, o);
    if (lane == 0) ssum[wid] = sum;
    __syncthreads();
    if (wid == 0) {
        float m = (lane < 4) ? ssum[lane] : 0.f;
        #pragma unroll
        for (int o = 2; o; o >>= 1) m += __shfl_xor_sync(0xffffffffu, m, o);
        if (lane == 0) ssum[0] = m;
    }
    __syncthreads();
    float inv = 1.0f / ssum[0];

    #pragma unroll
    for (int i = 0; i < 8; i++) {
        int s = tid + (i << 7);
        if (s < n) op[s] = v[i] * inv;
    }
}

// ---------------------------------------------------------------------------
// Pass D: A2[b,2g+k,l,s] = causal ? sum_j conv3x3_after(A[b,2g+j])[l,s]*hk[g,j,k] : 0
// Same tiling as Pass B. Writes zeros for s>l inside covered tiles so Pass E's
// diagonal k-tile reads clean zeros.
// ---------------------------------------------------------------------------
__global__ void convhead_kernel(const float* __restrict__ mta_after, const float* __restrict__ head_k)
{
    if (blockIdx.x > blockIdx.y) return;
    const int st = blockIdx.x << 5, lt = blockIdx.y << 5, b = blockIdx.z;
    const int tid = threadIdx.x;

    __shared__ float sm[8][34][35];
    __shared__ float kk[8][9];
    __shared__ float hk[16];
    if (tid < 72) kk[tid / 9][tid % 9] = mta_after[tid];
    if (tid < 16) hk[tid] = head_k[tid];

    const float* inb = g_buf1 + (size_t)b * 8 * PLANE;
    for (int idx = tid; idx < 8 * 34 * 34; idx += 256) {
        int h = idx / (34 * 34);
        int r = (idx / 34) % 34;
        int c = idx % 34;
        int gl = lt - 2 + r, gs = st - 1 + c;
        float v = 0.f;
        if (gl >= 0 && gs >= 0 && gs < 1024)
            v = inb[(size_t)h * PLANE + (size_t)gl * 1024 + gs];
        sm[h][r][c] = v;
    }
    __syncthreads();

    float* outb = g_buf2 + (size_t)b * 8 * PLANE;
    for (int p = tid; p < 1024; p += 256) {
        int li = p >> 5, si = p & 31;
        float c[8];
        #pragma unroll
        for (int h = 0; h < 8; h++) {
            float a = 0.f;
            #pragma unroll
            for (int i = 0; i < 3; i++)
                #pragma unroll
                for (int j = 0; j < 3; j++)
                    a += kk[h][i * 3 + j] * sm[h][li + i][si + j];
            c[h] = a;
        }
        int l = lt + li, s = st + si;
        bool cz = (s <= l);
        size_t off = (size_t)l * 1024 + s;
        #pragma unroll
        for (int g = 0; g < 4; g++) {
            // out[k] = sum_j c[2g+j] * hk[g][j][k];  hk layout [g][j][k] = hk[g*4+j*2+k]
            float o0 = c[2 * g] * hk[g * 4 + 0] + c[2 * g + 1] * hk[g * 4 + 2];
            float o1 = c[2 * g] * hk[g * 4 + 1] + c[2 * g + 1] * hk[g * 4 + 3];
            outb[(size_t)(2 * g)     * PLANE + off] = cz ? o0 : 0.f;
            outb[(size_t)(2 * g + 1) * PLANE + off] = cz ? o1 : 0.f;
        }
    }
}

// ---------------------------------------------------------------------------
// Pass E: out[b,l,h,e] = sum_s A2[b,h,l,s] * V[b,s,h,e].  Causal k-loop: s-tiles
// only up to the diagonal tile (A2 holds zeros above the diagonal there).
// grid (16, 32) = (l-tile, b*8+h), block (16,16), 64x64 tile, 4x4 per thread.
// ---------------------------------------------------------------------------
__global__ void av_kernel(const float* __restrict__ v, float* __restrict__ out)
{
    const int bh = blockIdx.y;
    const int b  = bh >> 3, h = bh & 7;
    const int l0 = blockIdx.x << 6;
    const int tx = threadIdx.x, ty = threadIdx.y;
    const int tid = ty * 16 + tx;

    __shared__ float As[64][65];
    __shared__ float Vs[64][65];
    const float* Ab = g_buf2 + (size_t)bh * PLANE;
    const float* vb = v + (size_t)b * L_ * 512 + h * 64;

    float acc[4][4];
    #pragma unroll
    for (int i = 0; i < 4; i++)
        #pragma unroll
        for (int j = 0; j < 4; j++) acc[i][j] = 0.f;

    for (int s0 = 0; s0 <= l0; s0 += 64) {
        #pragma unroll
        for (int i = 0; i < 4; i++) {
            int row = (tid >> 4) + (i << 4);
            int c   = (tid & 15) << 2;
            float4 av = *(const float4*)&Ab[(size_t)(l0 + row) * 1024 + s0 + c];
            As[row][c] = av.x; As[row][c+1] = av.y; As[row][c+2] = av.z; As[row][c+3] = av.w;
            float4 vv = *(const float4*)&vb[(size_t)(s0 + row) * 512 + c];
            Vs[row][c] = vv.x; Vs[row][c+1] = vv.y; Vs[row][c+2] = vv.z; Vs[row][c+3] = vv.w;
        }
        __syncthreads();
        #pragma unroll
        for (int kx = 0; kx < 64; kx++) {
            float a[4], vv[4];
            #pragma unroll
            for (int i = 0; i < 4; i++) a[i] = As[ty * 4 + i][kx];
            #pragma unroll
            for (int j = 0; j < 4; j++) vv[j] = Vs[kx][tx * 4 + j];
            #pragma unroll
            for (int i = 0; i < 4; i++)
                #pragma unroll
                for (int j = 0; j < 4; j++) acc[i][j] += a[i] * vv[j];
        }
        __syncthreads();
    }

    #pragma unroll
    for (int i = 0; i < 4; i++) {
        int l = l0 + ty * 4 + i;
        int e = tx * 4;
        float4 r = make_float4(acc[i][0], acc[i][1], acc[i][2], acc[i][3]);
        *(float4*)&out[((size_t)(b * L_ + l) * H_ + h) * E_ + e] = r;
    }
}

// ---------------------------------------------------------------------------
extern "C" void kernel_launch(void* const* d_in, const int* in_sizes, int n_in,
                              void* d_out, int out_size)
{
    const float* q         = (const float*)d_in[0];
    const float* k         = (const float*)d_in[1];
    const float* v         = (const float*)d_in[2];
    const float* mta       = (const float*)d_in[3];
    const float* mta_after = (const float*)d_in[4];
    const float* head_k    = (const float*)d_in[5];
    const float* wpsm      = (const float*)d_in[6];
    float* out = (float*)d_out;

    dim3 bA(16, 16);
    dim3 gA(16, 16, 32);
    qk_kernel<<<gA, bA>>>(q, k);

    dim3 gB(32, 32, 4);
    convmix_kernel<<<gB, 256>>>(mta, wpsm);

    softmax_kernel<<<32768, 128>>>();

    convhead_kernel<<<gB, 256>>>(mta_after, head_k);

    dim3 gE(16, 32);
    av_kernel<<<gE, bA>>>(v, out);
}